// round 10
// baseline (speedup 1.0000x reference)
#include <cuda_runtime.h>

// IoU is translation- and scale-invariant (reference grid offsets cancel),
// so compute in grid-relative units; typo y1_t = cy_t + w_t/2 preserved.

#define CELLS_PER_IMG 49
#define LAMBDA_COORD 5.0f
#define LAMBDA_NOOBJ 0.1f
#define EPSF 1e-12f

#define NTHREADS 256
#define NWARPS (NTHREADS / 32)

__device__ double g_acc;   // zero-init in cubin; reset by finalize each launch

__device__ __forceinline__ float iou_f(float bx, float by, float bw, float bh,
                                       float tx, float ty, float tw, float th) {
    float x0p = fmaf(-3.5f, bw, bx), x1p = fmaf(3.5f, bw, bx);
    float y0p = fmaf(-3.5f, bh, by), y1p = fmaf(3.5f, bh, by);
    float x0t = fmaf(-3.5f, tw, tx), x1t = fmaf(3.5f, tw, tx);
    float y0t = fmaf(-3.5f, th, ty);
    float y1t = fmaf(3.5f, tw, ty);   // TYPO kept from reference: uses w_t
    float ux0 = fmaxf(x0p, x0t);
    float ux1 = fminf(x1p, x1t);
    float uy0 = fmaxf(y0p, y0t);
    float uy1 = fminf(y1p, y1t);
    bool valid = (ux0 < ux1) && (uy0 < uy1);
    float area_u = (ux1 - ux0) * (uy1 - uy0);
    float area_p = (49.0f * bw) * bh;
    float area_t = (7.0f * tw) * (y1t - y0t);
    float res = __fdividef(area_u, area_p + area_t - area_u + EPSF);
    return valid ? res : 0.0f;
}

__device__ __forceinline__ float cell_loss(float p0, float p1, float p2, float p3, float p4,
                                           float p5, float p6, float p7, float p8, float p9,
                                           float t0, float t1, float t2, float t3, float t4) {
    float iou0 = iou_f(p0, p1, p2, p3, t0, t1, t2, t3);
    float iou1 = iou_f(p5, p6, p7, p8, t0, t1, t2, t3);
    bool obj = (t4 == 1.0f);
    bool c0 = iou0 > iou1;
    float local;
    if (obj) {
        float conf_pre = c0 ? p4 : p9;
        float conf_true = c0 ? iou0 : iou1;
        float dc = conf_pre - conf_true;
        local = dc * dc;
        float dx = (c0 ? p0 : p5) - t0;
        float dy = (c0 ? p1 : p6) - t1;
        local += LAMBDA_COORD * (dx * dx + dy * dy);
        float wb = fmaxf(c0 ? p2 : p7, EPSF);
        float hb = fmaxf(c0 ? p3 : p8, EPSF);
        float wt = fmaxf(t2, EPSF);
        float ht = fmaxf(t3, EPSF);
        float dw = sqrtf(wb) - sqrtf(wt);
        float dh = sqrtf(hb) - sqrtf(ht);
        local += LAMBDA_COORD * (dw * dw + dh * dh);
    } else {
        local = LAMBDA_NOOBJ * (p4 * p4 + p9 * p9);
    }
    return local;
}

__global__ void __launch_bounds__(NTHREADS)
yolo_loss_main(const float* __restrict__ y_pre,
               const float* __restrict__ y_true,
               int n_cells) {
    __shared__ float s_pre[NWARPS][320];    // 32 cells x 10 floats per warp
    __shared__ float s_true[NWARPS][160];   // 32 cells x 5 floats per warp

    int tid = threadIdx.x;
    int lane = tid & 31;
    int wid = tid >> 5;
    int warp_base = (blockIdx.x * NWARPS + wid) * 32;   // first cell of this warp

    float local = 0.0f;

    if (warp_base + 32 <= n_cells) {
        // ---- coalesced staging: y_pre 80 float4, y_true 40 float4 per warp ----
        const float4* gp = (const float4*)y_pre + (size_t)warp_base * 10 / 4;
        float4* sp4 = (float4*)s_pre[wid];
        sp4[lane]      = __ldcs(gp + lane);
        sp4[lane + 32] = __ldcs(gp + lane + 32);
        if (lane < 16) sp4[lane + 64] = __ldcs(gp + lane + 64);

        const float4* gt = (const float4*)y_true + (size_t)warp_base * 5 / 4;
        float4* st4 = (float4*)s_true[wid];
        st4[lane] = __ldcs(gt + lane);
        if (lane < 8) st4[lane + 32] = __ldcs(gt + lane + 32);

        __syncwarp();

        const float* sp = &s_pre[wid][lane * 10];
        const float* st = &s_true[wid][lane * 5];
        // lane*10 floats = 40B offset -> 8B aligned, read as float2
        const float2* sp2 = (const float2*)sp;
        float2 p01 = sp2[0], p23 = sp2[1], p45 = sp2[2], p67 = sp2[3], p89 = sp2[4];

        local = cell_loss(p01.x, p01.y, p23.x, p23.y, p45.x,
                          p45.y, p67.x, p67.y, p89.x, p89.y,
                          st[0], st[1], st[2], st[3], st[4]);
    } else {
        // ---- tail warp: direct global loads with bounds ----
        int idx = warp_base + lane;
        if (idx < n_cells) {
            const float2* p = (const float2*)(y_pre + (size_t)idx * 10);
            float2 p01 = p[0], p23 = p[1], p45 = p[2], p67 = p[3], p89 = p[4];
            const float* t = y_true + (size_t)idx * 5;
            local = cell_loss(p01.x, p01.y, p23.x, p23.y, p45.x,
                              p45.y, p67.x, p67.y, p89.x, p89.y,
                              t[0], t[1], t[2], t[3], t[4]);
        }
    }

    // ---- block reduction (fp32) ----
    #pragma unroll
    for (int off = 16; off > 0; off >>= 1)
        local += __shfl_down_sync(0xFFFFFFFFu, local, off);

    __shared__ float warp_sums[NWARPS];
    if (lane == 0) warp_sums[wid] = local;
    __syncthreads();

    if (wid == 0) {
        float v = (lane < NWARPS) ? warp_sums[lane] : 0.0f;
        #pragma unroll
        for (int off = 4; off > 0; off >>= 1)
            v += __shfl_down_sync(0xFFFFFFFFu, v, off);
        if (lane == 0)
            atomicAdd(&g_acc, (double)v);   // fire-and-forget RED.f64; no fence
    }
}

__global__ void finalize_kernel(float* __restrict__ out, float inv_b) {
    // PDL: resident during the main grid; parks until main completes
    // (completion implies visibility of all REDs).
    asm volatile("griddepcontrol.wait;" ::: "memory");
    out[0] = (float)(g_acc * (double)inv_b);
    g_acc = 0.0;   // re-arm accumulator for next graph replay
}

extern "C" void kernel_launch(void* const* d_in, const int* in_sizes, int n_in,
                              void* d_out, int out_size) {
    const float* y_pre = (const float*)d_in[0];
    const float* y_true = (const float*)d_in[1];
    float* out = (float*)d_out;

    int n_cells = in_sizes[1] / 5;               // B * 49
    int B = n_cells / CELLS_PER_IMG;
    float inv_b = 1.0f / (float)B;

    int grid = (n_cells + NTHREADS - 1) / NTHREADS;
    yolo_loss_main<<<grid, NTHREADS>>>(y_pre, y_true, n_cells);

    // Programmatic dependent launch for the epilogue node.
    cudaLaunchConfig_t cfg = {};
    cfg.gridDim = dim3(1, 1, 1);
    cfg.blockDim = dim3(1, 1, 1);
    cfg.dynamicSmemBytes = 0;
    cfg.stream = 0;
    cudaLaunchAttribute attrs[1];
    attrs[0].id = cudaLaunchAttributeProgrammaticStreamSerialization;
    attrs[0].val.programmaticStreamSerializationAllowed = 1;
    cfg.attrs = attrs;
    cfg.numAttrs = 1;
    cudaLaunchKernelEx(&cfg, finalize_kernel, out, inv_b);
}

// round 11
// speedup vs baseline: 1.0222x; 1.0222x over previous
#include <cuda_runtime.h>

// IoU is translation- and scale-invariant (reference grid offsets cancel),
// so compute in grid-relative units; typo y1_t = cy_t + w_t/2 preserved.

#define CELLS_PER_IMG 49
#define LAMBDA_COORD 5.0f
#define LAMBDA_NOOBJ 0.1f
#define EPSF 1e-12f

#define NTHREADS 512
#define NWARPS (NTHREADS / 32)

__device__ __forceinline__ float iou_f(float bx, float by, float bw, float bh,
                                       float tx, float ty, float tw, float th) {
    float x0p = fmaf(-3.5f, bw, bx), x1p = fmaf(3.5f, bw, bx);
    float y0p = fmaf(-3.5f, bh, by), y1p = fmaf(3.5f, bh, by);
    float x0t = fmaf(-3.5f, tw, tx), x1t = fmaf(3.5f, tw, tx);
    float y0t = fmaf(-3.5f, th, ty);
    float y1t = fmaf(3.5f, tw, ty);   // TYPO kept from reference: uses w_t
    float ux0 = fmaxf(x0p, x0t);
    float ux1 = fminf(x1p, x1t);
    float uy0 = fmaxf(y0p, y0t);
    float uy1 = fminf(y1p, y1t);
    bool valid = (ux0 < ux1) && (uy0 < uy1);
    float area_u = (ux1 - ux0) * (uy1 - uy0);
    float area_p = (49.0f * bw) * bh;
    float area_t = (7.0f * tw) * (y1t - y0t);
    float res = __fdividef(area_u, area_p + area_t - area_u + EPSF);
    return valid ? res : 0.0f;
}

__global__ void __launch_bounds__(NTHREADS)
yolo_loss_main(const float* __restrict__ y_pre,
               const float* __restrict__ y_true,
               int n_cells, float inv_b, float* __restrict__ out) {
    int tid = threadIdx.x;
    int idx = blockIdx.x * NTHREADS + tid;

    float local = 0.0f;
    if (idx < n_cells) {
        // y_pre cell: 10 floats, 40B stride -> 8B aligned -> float2 loads
        const float2* p = (const float2*)(y_pre + (size_t)idx * 10);
        float2 p01 = p[0];
        float2 p23 = p[1];
        float2 p45 = p[2];
        float2 p67 = p[3];
        float2 p89 = p[4];

        const float* t = y_true + (size_t)idx * 5;
        float t0 = t[0], t1 = t[1], t2 = t[2], t3 = t[3], t4 = t[4];

        float iou0 = iou_f(p01.x, p01.y, p23.x, p23.y, t0, t1, t2, t3);
        float iou1 = iou_f(p45.y, p67.x, p67.y, p89.x, t0, t1, t2, t3);

        bool obj = (t4 == 1.0f);
        bool c0 = iou0 > iou1;

        if (obj) {
            float conf_pre = c0 ? p45.x : p89.y;
            float conf_true = c0 ? iou0 : iou1;
            float dc = conf_pre - conf_true;
            local = dc * dc;
            float dx = (c0 ? p01.x : p45.y) - t0;
            float dy = (c0 ? p01.y : p67.x) - t1;
            local += LAMBDA_COORD * (dx * dx + dy * dy);
            float wb = fmaxf(c0 ? p23.x : p67.y, EPSF);
            float hb = fmaxf(c0 ? p23.y : p89.x, EPSF);
            float wt = fmaxf(t2, EPSF);
            float ht = fmaxf(t3, EPSF);
            float dw = sqrtf(wb) - sqrtf(wt);
            float dh = sqrtf(hb) - sqrtf(ht);
            local += LAMBDA_COORD * (dw * dw + dh * dh);
        } else {
            local = LAMBDA_NOOBJ * (p45.x * p45.x + p89.y * p89.y);
        }
    }

    // ---- block reduction (fp32) ----
    #pragma unroll
    for (int off = 16; off > 0; off >>= 1)
        local += __shfl_down_sync(0xFFFFFFFFu, local, off);

    __shared__ float warp_sums[NWARPS];
    int lane = tid & 31;
    int wid = tid >> 5;
    if (lane == 0) warp_sums[wid] = local;
    __syncthreads();

    if (wid == 0) {
        float v = (lane < NWARPS) ? warp_sums[lane] : 0.0f;
        #pragma unroll
        for (int off = 8; off > 0; off >>= 1)
            v += __shfl_down_sync(0xFFFFFFFFu, v, off);
        if (lane == 0)
            atomicAdd(out, v * inv_b);   // fire-and-forget RED.f32, pre-scaled
    }
}

extern "C" void kernel_launch(void* const* d_in, const int* in_sizes, int n_in,
                              void* d_out, int out_size) {
    const float* y_pre = (const float*)d_in[0];
    const float* y_true = (const float*)d_in[1];
    float* out = (float*)d_out;

    int n_cells = in_sizes[1] / 5;               // B * 49
    int B = n_cells / CELLS_PER_IMG;
    float inv_b = 1.0f / (float)B;

    // zero the scalar output (graph-capturable memset node), then accumulate
    cudaMemsetAsync(out, 0, sizeof(float), 0);

    int grid = (n_cells + NTHREADS - 1) / NTHREADS;
    yolo_loss_main<<<grid, NTHREADS>>>(y_pre, y_true, n_cells, inv_b, out);
}

// round 12
// speedup vs baseline: 1.0396x; 1.0170x over previous
#include <cuda_runtime.h>

// IoU is translation- and scale-invariant (reference grid offsets cancel),
// so compute in grid-relative units; typo y1_t = cy_t + w_t/2 preserved.

#define CELLS_PER_IMG 49
#define LAMBDA_COORD 5.0f
#define LAMBDA_NOOBJ 0.1f
#define EPSF 1e-12f

#define NTHREADS 256
#define NWARPS (NTHREADS / 32)

__device__ __forceinline__ float iou_f(float bx, float by, float bw, float bh,
                                       float tx, float ty, float tw, float th) {
    float x0p = fmaf(-3.5f, bw, bx), x1p = fmaf(3.5f, bw, bx);
    float y0p = fmaf(-3.5f, bh, by), y1p = fmaf(3.5f, bh, by);
    float x0t = fmaf(-3.5f, tw, tx), x1t = fmaf(3.5f, tw, tx);
    float y0t = fmaf(-3.5f, th, ty);
    float y1t = fmaf(3.5f, tw, ty);   // TYPO kept from reference: uses w_t
    float ux0 = fmaxf(x0p, x0t);
    float ux1 = fminf(x1p, x1t);
    float uy0 = fmaxf(y0p, y0t);
    float uy1 = fminf(y1p, y1t);
    bool valid = (ux0 < ux1) && (uy0 < uy1);
    float area_u = (ux1 - ux0) * (uy1 - uy0);
    float area_p = (49.0f * bw) * bh;
    float area_t = (7.0f * tw) * (y1t - y0t);
    float res = __fdividef(area_u, area_p + area_t - area_u + EPSF);
    return valid ? res : 0.0f;
}

// Primary: zero the scalar output, then release PDL dependents early.
__global__ void zero_out_kernel(float* __restrict__ out) {
    out[0] = 0.0f;
    asm volatile("griddepcontrol.launch_dependents;" ::: "memory");
}

__global__ void __launch_bounds__(NTHREADS)
yolo_loss_main(const float* __restrict__ y_pre,
               const float* __restrict__ y_true,
               int n_cells, float inv_b, float* __restrict__ out) {
    int tid = threadIdx.x;
    int idx = blockIdx.x * NTHREADS + tid;

    float local = 0.0f;
    if (idx < n_cells) {
        // y_pre cell: 10 floats, 40B stride -> 8B aligned -> float2 loads
        const float2* p = (const float2*)(y_pre + (size_t)idx * 10);
        float2 p01 = p[0];
        float2 p23 = p[1];
        float2 p45 = p[2];
        float2 p67 = p[3];
        float2 p89 = p[4];

        const float* t = y_true + (size_t)idx * 5;
        float t0 = t[0], t1 = t[1], t2 = t[2], t3 = t[3], t4 = t[4];

        float iou0 = iou_f(p01.x, p01.y, p23.x, p23.y, t0, t1, t2, t3);
        float iou1 = iou_f(p45.y, p67.x, p67.y, p89.x, t0, t1, t2, t3);

        bool obj = (t4 == 1.0f);
        bool c0 = iou0 > iou1;

        if (obj) {
            float conf_pre = c0 ? p45.x : p89.y;
            float conf_true = c0 ? iou0 : iou1;
            float dc = conf_pre - conf_true;
            local = dc * dc;
            float dx = (c0 ? p01.x : p45.y) - t0;
            float dy = (c0 ? p01.y : p67.x) - t1;
            local += LAMBDA_COORD * (dx * dx + dy * dy);
            float wb = fmaxf(c0 ? p23.x : p67.y, EPSF);
            float hb = fmaxf(c0 ? p23.y : p89.x, EPSF);
            float wt = fmaxf(t2, EPSF);
            float ht = fmaxf(t3, EPSF);
            float dw = sqrtf(wb) - sqrtf(wt);
            float dh = sqrtf(hb) - sqrtf(ht);
            local += LAMBDA_COORD * (dw * dw + dh * dh);
        } else {
            local = LAMBDA_NOOBJ * (p45.x * p45.x + p89.y * p89.y);
        }
    }

    // ---- block reduction (fp32) ----
    #pragma unroll
    for (int off = 16; off > 0; off >>= 1)
        local += __shfl_down_sync(0xFFFFFFFFu, local, off);

    __shared__ float warp_sums[NWARPS];
    int lane = tid & 31;
    int wid = tid >> 5;
    if (lane == 0) warp_sums[wid] = local;
    __syncthreads();

    if (wid == 0) {
        float v = (lane < NWARPS) ? warp_sums[lane] : 0.0f;
        #pragma unroll
        for (int off = 4; off > 0; off >>= 1)
            v += __shfl_down_sync(0xFFFFFFFFu, v, off);
        if (lane == 0) {
            // Ensure the zeroing primary has finished before accumulating.
            // By the time any block gets here the primary completed ~us ago,
            // so this is a fast-path TRYWAIT (~90cyc), not a real stall.
            asm volatile("griddepcontrol.wait;" ::: "memory");
            atomicAdd(out, v * inv_b);   // fire-and-forget RED.f32, pre-scaled
        }
    }
}

extern "C" void kernel_launch(void* const* d_in, const int* in_sizes, int n_in,
                              void* d_out, int out_size) {
    const float* y_pre = (const float*)d_in[0];
    const float* y_true = (const float*)d_in[1];
    float* out = (float*)d_out;

    int n_cells = in_sizes[1] / 5;               // B * 49
    int B = n_cells / CELLS_PER_IMG;
    float inv_b = 1.0f / (float)B;

    // Primary node: zero out[0] (tiny kernel, releases dependents early).
    zero_out_kernel<<<1, 1>>>(out);

    // Secondary (PDL): main kernel overlaps the primary's launch/drain —
    // its blocks start loading immediately; only the final atomic is gated
    // on primary completion via griddepcontrol.wait.
    int grid = (n_cells + NTHREADS - 1) / NTHREADS;
    cudaLaunchConfig_t cfg = {};
    cfg.gridDim = dim3((unsigned)grid, 1, 1);
    cfg.blockDim = dim3(NTHREADS, 1, 1);
    cfg.dynamicSmemBytes = 0;
    cfg.stream = 0;
    cudaLaunchAttribute attrs[1];
    attrs[0].id = cudaLaunchAttributeProgrammaticStreamSerialization;
    attrs[0].val.programmaticStreamSerializationAllowed = 1;
    cfg.attrs = attrs;
    cfg.numAttrs = 1;
    cudaLaunchKernelEx(&cfg, yolo_loss_main, y_pre, y_true, n_cells, inv_b, out);
}